// round 3
// baseline (speedup 1.0000x reference)
#include <cuda_runtime.h>
#include <cuda_bf16.h>
#include <cstdint>

// ----------------------------------------------------------------------------
// GroupedLinear: out[t,n] = sum_k inp[t,k] * weight[e,n,k],  e = t / 2048
// Base-ISA path (harness PTX targets sm_103 WITHOUT 'a' -> no tcgen05/TMA).
// 3-term bf16 split (A_hi*W_hi + A_lo*W_hi + A_hi*W_lo) as ONE virtual
// K'=12288 GEMM via chunk remap into [hi|lo] bf16 scratch.
// GEMM: mma.sync.m16n8k16 bf16 + ldmatrix + cp.async 3-stage pipeline.
// R2 fixes: correct B-fragment pairing {r[h], r[h+2]}; no static guards.
// ----------------------------------------------------------------------------

#define E_EXPERTS 8
#define DIN 4096
#define DOUT 4096
#define T_TOK 16384
#define KPRIME 8192            // bf16 scratch row: [hi(4096) | lo(4096)]
#define ROWBYTES (KPRIME * 2)  // 16384 bytes per scratch row

#define CTA_M 256
#define CTA_N 128
#define KCHUNK 32              // bf16 elems per chunk = 64 bytes
#define NCHUNKS 384            // 3 * 4096 / 32 virtual K' chunks
#define THREADS 256
#define STAGES 3

#define SROW 80                                 // padded smem row stride (bytes)
#define A_STAGE_BYTES (CTA_M * SROW)            // 20480
#define B_STAGE_BYTES (CTA_N * SROW)            // 10240
#define STAGE_BYTES (A_STAGE_BYTES + B_STAGE_BYTES)  // 30720
#define SMEM_BYTES (STAGES * STAGE_BYTES)       // 92160

__device__ __nv_bfloat16 g_A[(size_t)T_TOK * KPRIME];                 // 256 MB
__device__ __nv_bfloat16 g_B[(size_t)E_EXPERTS * DOUT * KPRIME];      // 512 MB

// ---------------- low-level helpers -----------------------------------------

__device__ __forceinline__ uint32_t smem_to_u32(const void* smem_ptr) {
    uint32_t addr;
    asm("{ .reg .u64 tmp; cvta.to.shared.u64 tmp, %1; cvt.u32.u64 %0, tmp; }"
        : "=r"(addr) : "l"(smem_ptr));
    return addr;
}

__device__ __forceinline__ void cp16(uint32_t s, const void* g) {
    asm volatile("cp.async.cg.shared.global [%0], [%1], 16;"
                 :: "r"(s), "l"(g) : "memory");
}
__device__ __forceinline__ void cp_commit() {
    asm volatile("cp.async.commit_group;" ::: "memory");
}
#define CP_WAIT(n) asm volatile("cp.async.wait_group %0;" :: "n"(n) : "memory")

__device__ __forceinline__ void ldsm_x4(uint32_t* r, uint32_t addr) {
    asm volatile("ldmatrix.sync.aligned.m8n8.x4.shared.b16 {%0,%1,%2,%3}, [%4];"
                 : "=r"(r[0]), "=r"(r[1]), "=r"(r[2]), "=r"(r[3]) : "r"(addr));
}

__device__ __forceinline__ void mma_16816(float* d, const uint32_t* a,
                                          uint32_t b0, uint32_t b1) {
    asm volatile(
        "mma.sync.aligned.m16n8k16.row.col.f32.bf16.bf16.f32 "
        "{%0,%1,%2,%3}, {%4,%5,%6,%7}, {%8,%9}, {%0,%1,%2,%3};"
        : "+f"(d[0]), "+f"(d[1]), "+f"(d[2]), "+f"(d[3])
        : "r"(a[0]), "r"(a[1]), "r"(a[2]), "r"(a[3]), "r"(b0), "r"(b1));
}

// ---------------- conversion kernels (fp32 -> [hi|lo] bf16 scratch) ---------

__global__ void __launch_bounds__(THREADS) convA_kernel(const float* __restrict__ inp) {
    size_t i = (size_t)blockIdx.x * THREADS + threadIdx.x;  // one per 4 floats
    size_t t = i >> 10;
    int g = (int)(i & 1023);
    float4 v = __ldg(((const float4*)(inp + t * DIN)) + g);
    float fs[4] = {v.x, v.y, v.z, v.w};
    union { __nv_bfloat16 b[4]; uint2 u; } H, L;
#pragma unroll
    for (int j = 0; j < 4; ++j) {
        __nv_bfloat16 hb = __float2bfloat16(fs[j]);
        H.b[j] = hb;
        L.b[j] = __float2bfloat16(fs[j] - __bfloat162float(hb));
    }
    __nv_bfloat16* rowp = g_A + t * KPRIME;
    ((uint2*)(rowp))[g]       = H.u;
    ((uint2*)(rowp + DIN))[g] = L.u;
}

__global__ void __launch_bounds__(THREADS) convB_kernel(const float* __restrict__ w) {
    size_t i = (size_t)blockIdx.x * THREADS + threadIdx.x;
    size_t r = i >> 10;                                     // e*4096 + n
    int g = (int)(i & 1023);
    float4 v = __ldg(((const float4*)(w + r * DIN)) + g);
    float fs[4] = {v.x, v.y, v.z, v.w};
    union { __nv_bfloat16 b[4]; uint2 u; } H, L;
#pragma unroll
    for (int j = 0; j < 4; ++j) {
        __nv_bfloat16 hb = __float2bfloat16(fs[j]);
        H.b[j] = hb;
        L.b[j] = __float2bfloat16(fs[j] - __bfloat162float(hb));
    }
    __nv_bfloat16* rowp = g_B + r * KPRIME;
    ((uint2*)(rowp))[g]       = H.u;
    ((uint2*)(rowp + DIN))[g] = L.u;
}

// ---------------- GEMM kernel ------------------------------------------------

__global__ void __launch_bounds__(THREADS, 1) gemm_kernel(float* __restrict__ out) {
    extern __shared__ char smem[];
    const uint32_t smem_u32 = smem_to_u32(smem);
    const int tid = threadIdx.x;
    const int wid = tid >> 5;
    const int lid = tid & 31;

    // Tile decode: N-fastest so concurrent CTAs share A strips + expert B in L2
    const int bx = blockIdx.x;
    const int n_tile = bx & 31;           // 32 N-tiles of 128
    const int m_tile = bx >> 5;           // 64 M-tiles of 256
    const int e = m_tile >> 3;            // 2048 tokens / 256 rows = 8 m-tiles

    const char* Abase = (const char*)(g_A + (size_t)(m_tile * CTA_M) * KPRIME);
    const char* Bbase = (const char*)(g_B + ((size_t)e * DOUT +
                                             (size_t)n_tile * CTA_N) * KPRIME);

    uint32_t sA[STAGES], sB[STAGES];
#pragma unroll
    for (int s = 0; s < STAGES; ++s) {
        sA[s] = smem_u32 + s * STAGE_BYTES;
        sB[s] = sA[s] + A_STAGE_BYTES;
    }

    // A: 256 rows x 4 groups(16B) = 1024 cp; B: 128 x 4 = 512 cp; 6 per thread.
    const int l_row_a = tid >> 2;         // rows tid/4, tid/4+64, ...
    const int l_grp   = (tid & 3) * 16;   // byte group within 64B chunk

#define ISSUE_STAGE(stg, c) do {                                              \
        int ac_ = ((c) < 256) ? (c) : (c) - 256;   /* A: [hi|lo|hi] */        \
        int bc_ = ((c) < 128) ? (c) : (c) - 128;   /* B: [hi|hi|lo] */        \
        const char* aG_ = Abase + (size_t)ac_ * 64;                           \
        const char* bG_ = Bbase + (size_t)bc_ * 64;                           \
        _Pragma("unroll")                                                     \
        for (int i_ = 0; i_ < 4; ++i_) {                                      \
            int row_ = l_row_a + i_ * 64;                                     \
            cp16(sA[stg] + row_ * SROW + l_grp,                               \
                 aG_ + (size_t)row_ * ROWBYTES + l_grp);                      \
        }                                                                     \
        _Pragma("unroll")                                                     \
        for (int i_ = 0; i_ < 2; ++i_) {                                      \
            int row_ = l_row_a + i_ * 64;                                     \
            cp16(sB[stg] + row_ * SROW + l_grp,                               \
                 bG_ + (size_t)row_ * ROWBYTES + l_grp);                      \
        }                                                                     \
    } while (0)

    // Warp layout: 4(M) x 2(N); warp tile 64x64.
    const int wm = wid >> 1;
    const int wn = wid & 1;

    // ldmatrix lane addressing (non-trans, both operands K-major):
    // lanes 0-7: rows r0..r0+7 @ byte 0; 8-15: rows+8 @ 0; 16-23: rows @ +16; 24-31: rows+8 @ +16
    const int lm_row = lid & 15;
    const int lm_col = (lid >> 4) * 16;

    float acc[4][8][4];
#pragma unroll
    for (int i = 0; i < 4; ++i)
#pragma unroll
        for (int j = 0; j < 8; ++j)
#pragma unroll
            for (int q = 0; q < 4; ++q) acc[i][j][q] = 0.0f;

    // Prologue: issue 2 stages
    ISSUE_STAGE(0, 0); cp_commit();
    ISSUE_STAGE(1, 1); cp_commit();

#pragma unroll 1
    for (int c = 0; c < NCHUNKS; ++c) {
        CP_WAIT(1);
        __syncthreads();

        if (c + 2 < NCHUNKS) {
            int stg = (c + 2) % STAGES;
            ISSUE_STAGE(stg, c + 2);
        }
        cp_commit();   // unconditional: keeps wait_group(1) group-counting correct

        const int cur = c % STAGES;
        const uint32_t aBase = sA[cur] + (wm * 64 + lm_row) * SROW + lm_col;
        const uint32_t bBase = sB[cur] + (wn * 64 + lm_row) * SROW + lm_col;

#pragma unroll
        for (int ks = 0; ks < 2; ++ks) {
            uint32_t af[4][4];
            uint32_t bf[4][4];
#pragma unroll
            for (int mf = 0; mf < 4; ++mf)
                ldsm_x4(af[mf], aBase + mf * (16 * SROW) + ks * 32);
#pragma unroll
            for (int nf2 = 0; nf2 < 4; ++nf2)
                ldsm_x4(bf[nf2], bBase + nf2 * (16 * SROW) + ks * 32);
#pragma unroll
            for (int mf = 0; mf < 4; ++mf)
#pragma unroll
                for (int nf = 0; nf < 8; ++nf) {
                    // B fragment pairing: within ldsm.x4 result,
                    // n-half h = nf&1 selects regs {h, h+2} = {k0-7, k8-15}.
                    const int g = nf >> 1, h = nf & 1;
                    mma_16816(acc[mf][nf], af[mf], bf[g][h], bf[g][h + 2]);
                }
        }
        __syncthreads();
    }

    // Epilogue: direct STG, float2 per (frag, row-half).
    const int row0 = m_tile * CTA_M + wm * 64 + (lid >> 2);
    const int col0 = n_tile * CTA_N + wn * 64 + (lid & 3) * 2;
#pragma unroll
    for (int mf = 0; mf < 4; ++mf) {
#pragma unroll
        for (int nf = 0; nf < 8; ++nf) {
            float* p0 = out + (size_t)(row0 + mf * 16) * DOUT + col0 + nf * 8;
            float* p1 = p0 + 8 * DOUT;
            *(float2*)p0 = make_float2(acc[mf][nf][0], acc[mf][nf][1]);
            *(float2*)p1 = make_float2(acc[mf][nf][2], acc[mf][nf][3]);
        }
    }
#undef ISSUE_STAGE
}

// ---------------- launch ------------------------------------------------------

extern "C" void kernel_launch(void* const* d_in, const int* in_sizes, int n_in,
                              void* d_out, int out_size) {
    (void)in_sizes; (void)n_in; (void)out_size;
    const float* inp = (const float*)d_in[0];
    const float* w   = (const float*)d_in[1];
    float* out       = (float*)d_out;

    convA_kernel<<<(T_TOK * (DIN / 4)) / THREADS, THREADS>>>(inp);
    convB_kernel<<<(E_EXPERTS * DOUT * (DIN / 4)) / THREADS, THREADS>>>(w);

    cudaFuncSetAttribute(gemm_kernel,
                         cudaFuncAttributeMaxDynamicSharedMemorySize,
                         SMEM_BYTES);
    gemm_kernel<<<(T_TOK / CTA_M) * (DOUT / CTA_N), THREADS, SMEM_BYTES>>>(out);
}

// round 4
// speedup vs baseline: 2.8816x; 2.8816x over previous
#include <cuda_runtime.h>
#include <cuda_fp16.h>
#include <cstdint>

// ----------------------------------------------------------------------------
// GroupedLinear: out[t,n] = sum_k inp[t,k] * weight[e,n,k],  e = t / 2048
// Base-ISA path (harness targets sm_103 without 'a' -> no tcgen05/TMA).
// R3 finding: mma.sync legacy pipe ceiling ~271 TF/s; kernel sits at 99% of it.
// R4: cut tensor work 3x -> SINGLE fp16 GEMM (K=4096). fp16 dual-operand
// rounding gives concentrated rel_err ~2.8e-4 < 1e-3 threshold.
// GEMM: mma.sync.m16n8k16.f16 + ldmatrix + cp.async 3-stage pipeline.
// ----------------------------------------------------------------------------

#define E_EXPERTS 8
#define DIN 4096
#define DOUT 4096
#define T_TOK 16384
#define ROWBYTES (DIN * 2)     // 8192 bytes per fp16 scratch row

#define CTA_M 256
#define CTA_N 128
#define NCHUNKS 128            // 4096 / 32 K-chunks
#define THREADS 256
#define STAGES 3

#define SROW 80                                 // padded smem row stride (bytes)
#define A_STAGE_BYTES (CTA_M * SROW)            // 20480
#define B_STAGE_BYTES (CTA_N * SROW)            // 10240
#define STAGE_BYTES (A_STAGE_BYTES + B_STAGE_BYTES)  // 30720
#define SMEM_BYTES (STAGES * STAGE_BYTES)       // 92160

__device__ __half g_A[(size_t)T_TOK * DIN];                 // 128 MB
__device__ __half g_B[(size_t)E_EXPERTS * DOUT * DIN];      // 256 MB

// ---------------- low-level helpers -----------------------------------------

__device__ __forceinline__ uint32_t smem_to_u32(const void* smem_ptr) {
    uint32_t addr;
    asm("{ .reg .u64 tmp; cvta.to.shared.u64 tmp, %1; cvt.u32.u64 %0, tmp; }"
        : "=r"(addr) : "l"(smem_ptr));
    return addr;
}

__device__ __forceinline__ void cp16(uint32_t s, const void* g) {
    asm volatile("cp.async.cg.shared.global [%0], [%1], 16;"
                 :: "r"(s), "l"(g) : "memory");
}
__device__ __forceinline__ void cp_commit() {
    asm volatile("cp.async.commit_group;" ::: "memory");
}
#define CP_WAIT(n) asm volatile("cp.async.wait_group %0;" :: "n"(n) : "memory")

__device__ __forceinline__ void ldsm_x4(uint32_t* r, uint32_t addr) {
    asm volatile("ldmatrix.sync.aligned.m8n8.x4.shared.b16 {%0,%1,%2,%3}, [%4];"
                 : "=r"(r[0]), "=r"(r[1]), "=r"(r[2]), "=r"(r[3]) : "r"(addr));
}

__device__ __forceinline__ void mma_16816(float* d, const uint32_t* a,
                                          uint32_t b0, uint32_t b1) {
    asm volatile(
        "mma.sync.aligned.m16n8k16.row.col.f32.f16.f16.f32 "
        "{%0,%1,%2,%3}, {%4,%5,%6,%7}, {%8,%9}, {%0,%1,%2,%3};"
        : "+f"(d[0]), "+f"(d[1]), "+f"(d[2]), "+f"(d[3])
        : "r"(a[0]), "r"(a[1]), "r"(a[2]), "r"(a[3]), "r"(b0), "r"(b1));
}

// ---------------- conversion kernels (fp32 -> fp16 scratch) ------------------

__global__ void __launch_bounds__(THREADS) convA_kernel(const float* __restrict__ inp) {
    size_t i = (size_t)blockIdx.x * THREADS + threadIdx.x;  // one per 4 floats
    float4 v = __ldg(((const float4*)inp) + i);
    union { __half h[4]; uint2 u; } H;
    H.h[0] = __float2half_rn(v.x);
    H.h[1] = __float2half_rn(v.y);
    H.h[2] = __float2half_rn(v.z);
    H.h[3] = __float2half_rn(v.w);
    ((uint2*)g_A)[i] = H.u;
}

__global__ void __launch_bounds__(THREADS) convB_kernel(const float* __restrict__ w) {
    size_t i = (size_t)blockIdx.x * THREADS + threadIdx.x;
    float4 v = __ldg(((const float4*)w) + i);
    union { __half h[4]; uint2 u; } H;
    H.h[0] = __float2half_rn(v.x);
    H.h[1] = __float2half_rn(v.y);
    H.h[2] = __float2half_rn(v.z);
    H.h[3] = __float2half_rn(v.w);
    ((uint2*)g_B)[i] = H.u;
}

// ---------------- GEMM kernel ------------------------------------------------

__global__ void __launch_bounds__(THREADS, 1) gemm_kernel(float* __restrict__ out) {
    extern __shared__ char smem[];
    const uint32_t smem_u32 = smem_to_u32(smem);
    const int tid = threadIdx.x;
    const int wid = tid >> 5;
    const int lid = tid & 31;

    // Tile decode: N-fastest so concurrent CTAs share A strips + expert B in L2
    const int bx = blockIdx.x;
    const int n_tile = bx & 31;           // 32 N-tiles of 128
    const int m_tile = bx >> 5;           // 64 M-tiles of 256
    const int e = m_tile >> 3;            // 2048 tokens / 256 rows = 8 m-tiles

    const char* Abase = (const char*)(g_A + (size_t)(m_tile * CTA_M) * DIN);
    const char* Bbase = (const char*)(g_B + ((size_t)e * DOUT +
                                             (size_t)n_tile * CTA_N) * DIN);

    uint32_t sA[STAGES], sB[STAGES];
#pragma unroll
    for (int s = 0; s < STAGES; ++s) {
        sA[s] = smem_u32 + s * STAGE_BYTES;
        sB[s] = sA[s] + A_STAGE_BYTES;
    }

    // A: 256 rows x 4 groups(16B) = 1024 cp; B: 128 x 4 = 512 cp; 6 per thread.
    const int l_row_a = tid >> 2;         // rows tid/4, tid/4+64, ...
    const int l_grp   = (tid & 3) * 16;   // byte group within 64B chunk

#define ISSUE_STAGE(stg, c) do {                                              \
        const char* aG_ = Abase + (size_t)(c) * 64;                           \
        const char* bG_ = Bbase + (size_t)(c) * 64;                           \
        _Pragma("unroll")                                                     \
        for (int i_ = 0; i_ < 4; ++i_) {                                      \
            int row_ = l_row_a + i_ * 64;                                     \
            cp16(sA[stg] + row_ * SROW + l_grp,                               \
                 aG_ + (size_t)row_ * ROWBYTES + l_grp);                      \
        }                                                                     \
        _Pragma("unroll")                                                     \
        for (int i_ = 0; i_ < 2; ++i_) {                                      \
            int row_ = l_row_a + i_ * 64;                                     \
            cp16(sB[stg] + row_ * SROW + l_grp,                               \
                 bG_ + (size_t)row_ * ROWBYTES + l_grp);                      \
        }                                                                     \
    } while (0)

    // Warp layout: 4(M) x 2(N); warp tile 64x64.
    const int wm = wid >> 1;
    const int wn = wid & 1;

    // ldmatrix lane addressing (non-trans, both operands K-major)
    const int lm_row = lid & 15;
    const int lm_col = (lid >> 4) * 16;

    float acc[4][8][4];
#pragma unroll
    for (int i = 0; i < 4; ++i)
#pragma unroll
        for (int j = 0; j < 8; ++j)
#pragma unroll
            for (int q = 0; q < 4; ++q) acc[i][j][q] = 0.0f;

    // Prologue: issue 2 stages
    ISSUE_STAGE(0, 0); cp_commit();
    ISSUE_STAGE(1, 1); cp_commit();

#pragma unroll 1
    for (int c = 0; c < NCHUNKS; ++c) {
        CP_WAIT(1);
        __syncthreads();

        if (c + 2 < NCHUNKS) {
            int stg = (c + 2) % STAGES;
            ISSUE_STAGE(stg, c + 2);
        }
        cp_commit();   // unconditional: keeps wait_group(1) counting correct

        const int cur = c % STAGES;
        const uint32_t aBase = sA[cur] + (wm * 64 + lm_row) * SROW + lm_col;
        const uint32_t bBase = sB[cur] + (wn * 64 + lm_row) * SROW + lm_col;

#pragma unroll
        for (int ks = 0; ks < 2; ++ks) {
            uint32_t af[4][4];
            uint32_t bf[4][4];
#pragma unroll
            for (int mf = 0; mf < 4; ++mf)
                ldsm_x4(af[mf], aBase + mf * (16 * SROW) + ks * 32);
#pragma unroll
            for (int nf2 = 0; nf2 < 4; ++nf2)
                ldsm_x4(bf[nf2], bBase + nf2 * (16 * SROW) + ks * 32);
#pragma unroll
            for (int mf = 0; mf < 4; ++mf)
#pragma unroll
                for (int nf = 0; nf < 8; ++nf) {
                    // B pairing: n-half h = nf&1 -> regs {h, h+2} = {k0-7, k8-15}
                    const int g = nf >> 1, h = nf & 1;
                    mma_16816(acc[mf][nf], af[mf], bf[g][h], bf[g][h + 2]);
                }
        }
        __syncthreads();
    }

    // Epilogue: direct STG, float2 per (frag, row-half).
    const int row0 = m_tile * CTA_M + wm * 64 + (lid >> 2);
    const int col0 = n_tile * CTA_N + wn * 64 + (lid & 3) * 2;
#pragma unroll
    for (int mf = 0; mf < 4; ++mf) {
#pragma unroll
        for (int nf = 0; nf < 8; ++nf) {
            float* p0 = out + (size_t)(row0 + mf * 16) * DOUT + col0 + nf * 8;
            float* p1 = p0 + 8 * DOUT;
            *(float2*)p0 = make_float2(acc[mf][nf][0], acc[mf][nf][1]);
            *(float2*)p1 = make_float2(acc[mf][nf][2], acc[mf][nf][3]);
        }
    }
#undef ISSUE_STAGE
}

// ---------------- launch ------------------------------------------------------

extern "C" void kernel_launch(void* const* d_in, const int* in_sizes, int n_in,
                              void* d_out, int out_size) {
    (void)in_sizes; (void)n_in; (void)out_size;
    const float* inp = (const float*)d_in[0];
    const float* w   = (const float*)d_in[1];
    float* out       = (float*)d_out;

    convA_kernel<<<((size_t)T_TOK * DIN / 4) / THREADS, THREADS>>>(inp);
    convB_kernel<<<((size_t)E_EXPERTS * DOUT * DIN / 4) / THREADS, THREADS>>>(w);

    cudaFuncSetAttribute(gemm_kernel,
                         cudaFuncAttributeMaxDynamicSharedMemorySize,
                         SMEM_BYTES);
    gemm_kernel<<<(T_TOK / CTA_M) * (DOUT / CTA_N), THREADS, SMEM_BYTES>>>(out);
}

// round 6
// speedup vs baseline: 2.9004x; 1.0065x over previous
#include <cuda_runtime.h>
#include <cuda_fp16.h>
#include <cstdint>

// ----------------------------------------------------------------------------
// GroupedLinear: out[t,n] = sum_k inp[t,k] * weight[e,n,k],  e = t / 2048
// Base-ISA path (harness targets sm_103 without 'a' -> no tcgen05/TMA).
// R4: legacy HMMA.16816.F32 ~280 TF/s ceiling; GEMM at 98.3% of it.
// R5 bug: passed __device__ symbol as host-side kernel arg (host shadow
// address) -> scratch never written. Fix: conv kernels reference g_A/g_B
// from device code directly; keep MLP=4 vectorized conversion.
// GEMM: mma.sync.m16n8k16.f16 + ldmatrix + cp.async 3-stage pipeline.
// ----------------------------------------------------------------------------

#define E_EXPERTS 8
#define DIN 4096
#define DOUT 4096
#define T_TOK 16384
#define ROWBYTES (DIN * 2)     // 8192 bytes per fp16 scratch row

#define CTA_M 256
#define CTA_N 128
#define NCHUNKS 128            // 4096 / 32 K-chunks
#define THREADS 256
#define STAGES 3

#define SROW 80                                 // padded smem row stride (bytes)
#define A_STAGE_BYTES (CTA_M * SROW)            // 20480
#define B_STAGE_BYTES (CTA_N * SROW)            // 10240
#define STAGE_BYTES (A_STAGE_BYTES + B_STAGE_BYTES)  // 30720
#define SMEM_BYTES (STAGES * STAGE_BYTES)       // 92160

__device__ __half g_A[(size_t)T_TOK * DIN];                 // 128 MB
__device__ __half g_B[(size_t)E_EXPERTS * DOUT * DIN];      // 256 MB

// ---------------- low-level helpers -----------------------------------------

__device__ __forceinline__ uint32_t smem_to_u32(const void* smem_ptr) {
    uint32_t addr;
    asm("{ .reg .u64 tmp; cvta.to.shared.u64 tmp, %1; cvt.u32.u64 %0, tmp; }"
        : "=r"(addr) : "l"(smem_ptr));
    return addr;
}

__device__ __forceinline__ void cp16(uint32_t s, const void* g) {
    asm volatile("cp.async.cg.shared.global [%0], [%1], 16;"
                 :: "r"(s), "l"(g) : "memory");
}
__device__ __forceinline__ void cp_commit() {
    asm volatile("cp.async.commit_group;" ::: "memory");
}
#define CP_WAIT(n) asm volatile("cp.async.wait_group %0;" :: "n"(n) : "memory")

__device__ __forceinline__ void ldsm_x4(uint32_t* r, uint32_t addr) {
    asm volatile("ldmatrix.sync.aligned.m8n8.x4.shared.b16 {%0,%1,%2,%3}, [%4];"
                 : "=r"(r[0]), "=r"(r[1]), "=r"(r[2]), "=r"(r[3]) : "r"(addr));
}

__device__ __forceinline__ void mma_16816(float* d, const uint32_t* a,
                                          uint32_t b0, uint32_t b1) {
    asm volatile(
        "mma.sync.aligned.m16n8k16.row.col.f32.f16.f16.f32 "
        "{%0,%1,%2,%3}, {%4,%5,%6,%7}, {%8,%9}, {%0,%1,%2,%3};"
        : "+f"(d[0]), "+f"(d[1]), "+f"(d[2]), "+f"(d[3])
        : "r"(a[0]), "r"(a[1]), "r"(a[2]), "r"(a[3]), "r"(b0), "r"(b1));
}

// ---------------- conversion body (fp32 -> fp16, MLP=4) ----------------------
// Each thread: 4 x float4 loads (warp-contiguous 512B per instruction),
// 4 x 8B stores (warp-contiguous 256B). Block covers 4096 floats.

__device__ __forceinline__ void conv_body(const float* __restrict__ src,
                                          __half* __restrict__ dst) {
    const size_t blk = (size_t)blockIdx.x * 1024;   // float4 units
    const int tid = threadIdx.x;

    float4 v[4];
#pragma unroll
    for (int i = 0; i < 4; ++i)
        v[i] = __ldg(((const float4*)src) + blk + tid + i * 256);

#pragma unroll
    for (int i = 0; i < 4; ++i) {
        union { __half h[4]; uint2 u; } H;
        H.h[0] = __float2half_rn(v[i].x);
        H.h[1] = __float2half_rn(v[i].y);
        H.h[2] = __float2half_rn(v[i].z);
        H.h[3] = __float2half_rn(v[i].w);
        ((uint2*)dst)[blk + tid + i * 256] = H.u;
    }
}

// Device-code references to g_A/g_B (NEVER pass __device__ symbols from host!)
__global__ void __launch_bounds__(THREADS) convA_kernel(const float* __restrict__ inp) {
    conv_body(inp, g_A);
}
__global__ void __launch_bounds__(THREADS) convB_kernel(const float* __restrict__ w) {
    conv_body(w, g_B);
}

// ---------------- GEMM kernel ------------------------------------------------

__global__ void __launch_bounds__(THREADS, 1) gemm_kernel(float* __restrict__ out) {
    extern __shared__ char smem[];
    const uint32_t smem_u32 = smem_to_u32(smem);
    const int tid = threadIdx.x;
    const int wid = tid >> 5;
    const int lid = tid & 31;

    // Tile decode: N-fastest so concurrent CTAs share A strips + expert B in L2
    const int bx = blockIdx.x;
    const int n_tile = bx & 31;           // 32 N-tiles of 128
    const int m_tile = bx >> 5;           // 64 M-tiles of 256
    const int e = m_tile >> 3;            // 2048 tokens / 256 rows = 8 m-tiles

    const char* Abase = (const char*)(g_A + (size_t)(m_tile * CTA_M) * DIN);
    const char* Bbase = (const char*)(g_B + ((size_t)e * DOUT +
                                             (size_t)n_tile * CTA_N) * DIN);

    uint32_t sA[STAGES], sB[STAGES];
#pragma unroll
    for (int s = 0; s < STAGES; ++s) {
        sA[s] = smem_u32 + s * STAGE_BYTES;
        sB[s] = sA[s] + A_STAGE_BYTES;
    }

    // A: 256 rows x 4 groups(16B) = 1024 cp; B: 128 x 4 = 512 cp; 6 per thread.
    const int l_row_a = tid >> 2;         // rows tid/4, tid/4+64, ...
    const int l_grp   = (tid & 3) * 16;   // byte group within 64B chunk

#define ISSUE_STAGE(stg, c) do {                                              \
        const char* aG_ = Abase + (size_t)(c) * 64;                           \
        const char* bG_ = Bbase + (size_t)(c) * 64;                           \
        _Pragma("unroll")                                                     \
        for (int i_ = 0; i_ < 4; ++i_) {                                      \
            int row_ = l_row_a + i_ * 64;                                     \
            cp16(sA[stg] + row_ * SROW + l_grp,                               \
                 aG_ + (size_t)row_ * ROWBYTES + l_grp);                      \
        }                                                                     \
        _Pragma("unroll")                                                     \
        for (int i_ = 0; i_ < 2; ++i_) {                                      \
            int row_ = l_row_a + i_ * 64;                                     \
            cp16(sB[stg] + row_ * SROW + l_grp,                               \
                 bG_ + (size_t)row_ * ROWBYTES + l_grp);                      \
        }                                                                     \
    } while (0)

    // Warp layout: 4(M) x 2(N); warp tile 64x64.
    const int wm = wid >> 1;
    const int wn = wid & 1;

    // ldmatrix lane addressing (non-trans, both operands K-major)
    const int lm_row = lid & 15;
    const int lm_col = (lid >> 4) * 16;

    float acc[4][8][4];
#pragma unroll
    for (int i = 0; i < 4; ++i)
#pragma unroll
        for (int j = 0; j < 8; ++j)
#pragma unroll
            for (int q = 0; q < 4; ++q) acc[i][j][q] = 0.0f;

    // Prologue: issue 2 stages
    ISSUE_STAGE(0, 0); cp_commit();
    ISSUE_STAGE(1, 1); cp_commit();

#pragma unroll 1
    for (int c = 0; c < NCHUNKS; ++c) {
        CP_WAIT(1);
        __syncthreads();

        if (c + 2 < NCHUNKS) {
            int stg = (c + 2) % STAGES;
            ISSUE_STAGE(stg, c + 2);
        }
        cp_commit();   // unconditional: keeps wait_group(1) counting correct

        const int cur = c % STAGES;
        const uint32_t aBase = sA[cur] + (wm * 64 + lm_row) * SROW + lm_col;
        const uint32_t bBase = sB[cur] + (wn * 64 + lm_row) * SROW + lm_col;

#pragma unroll
        for (int ks = 0; ks < 2; ++ks) {
            uint32_t af[4][4];
            uint32_t bf[4][4];
#pragma unroll
            for (int mf = 0; mf < 4; ++mf)
                ldsm_x4(af[mf], aBase + mf * (16 * SROW) + ks * 32);
#pragma unroll
            for (int nf2 = 0; nf2 < 4; ++nf2)
                ldsm_x4(bf[nf2], bBase + nf2 * (16 * SROW) + ks * 32);
#pragma unroll
            for (int mf = 0; mf < 4; ++mf)
#pragma unroll
                for (int nf = 0; nf < 8; ++nf) {
                    // B pairing: n-half h = nf&1 -> regs {h, h+2} = {k0-7, k8-15}
                    const int g = nf >> 1, h = nf & 1;
                    mma_16816(acc[mf][nf], af[mf], bf[g][h], bf[g][h + 2]);
                }
        }
        __syncthreads();
    }

    // Epilogue: direct STG, float2 per (frag, row-half).
    const int row0 = m_tile * CTA_M + wm * 64 + (lid >> 2);
    const int col0 = n_tile * CTA_N + wn * 64 + (lid & 3) * 2;
#pragma unroll
    for (int mf = 0; mf < 4; ++mf) {
#pragma unroll
        for (int nf = 0; nf < 8; ++nf) {
            float* p0 = out + (size_t)(row0 + mf * 16) * DOUT + col0 + nf * 8;
            float* p1 = p0 + 8 * DOUT;
            *(float2*)p0 = make_float2(acc[mf][nf][0], acc[mf][nf][1]);
            *(float2*)p1 = make_float2(acc[mf][nf][2], acc[mf][nf][3]);
        }
    }
#undef ISSUE_STAGE
}

// ---------------- launch ------------------------------------------------------

extern "C" void kernel_launch(void* const* d_in, const int* in_sizes, int n_in,
                              void* d_out, int out_size) {
    (void)in_sizes; (void)n_in; (void)out_size;
    const float* inp = (const float*)d_in[0];
    const float* w   = (const float*)d_in[1];
    float* out       = (float*)d_out;

    // A: 16384*4096 floats / (4096 floats per block) = 16384 blocks
    convA_kernel<<<((size_t)T_TOK * DIN) / 4096, THREADS>>>(inp);
    // B: 8*4096*4096 floats / 4096 = 32768 blocks
    convB_kernel<<<((size_t)E_EXPERTS * DOUT * DIN) / 4096, THREADS>>>(w);

    cudaFuncSetAttribute(gemm_kernel,
                         cudaFuncAttributeMaxDynamicSharedMemorySize,
                         SMEM_BYTES);
    gemm_kernel<<<(T_TOK / CTA_M) * (DOUT / CTA_N), THREADS, SMEM_BYTES>>>(out);
}